// round 7
// baseline (speedup 1.0000x reference)
#include <cuda_runtime.h>
#include <cuda_bf16.h>
#include <cstdint>

// Problem constants
#define BSZ   4096
#define CDIM  128
#define NSUP  32768          // 4096*8 support rows
#define PIDS  256            // identity blocks (j = 0..255)
#define BLKC  128            // support columns per identity block
#define MTILE 128
#define MTILES (BSZ/MTILE)   // 32
#define TOTIT (MTILES*PIDS)  // 8192 (mtile, block) instances
#define NCTA  296            // 2 x 148 SMs
#define INV_TEMP 20.0f
#define EPSV 1e-6f
#define SROW 136             // smem row stride in bf16 (128+8 pad, conflict-free)

// Scratch (static device globals)
__device__ __nv_bfloat16 g_fs_bf[(size_t)NSUP * CDIM];      // 8 MB
__device__ float g_flushN[NCTA * 2 * MTILE];                // per (cta, t) neg partials
__device__ float g_flushP[NCTA * 2 * MTILE];                // per (cta, t) pos partials

__host__ __device__ __forceinline__ uint32_t range_start(uint32_t c) {
    return (uint32_t)(((uint64_t)c * TOTIT) / NCTA);
}

// ---------------------------------------------------------------------------
// Kernel 1: convert feats_s fp32 -> bf16 (2 float4 per thread)
// ---------------------------------------------------------------------------
__global__ void k_convert(const float* __restrict__ fs) {
    int i = (blockIdx.x * blockDim.x + threadIdx.x) * 2;    // float4 index
    float4 v0 = ((const float4*)fs)[i];
    float4 v1 = ((const float4*)fs)[i + 1];
    __nv_bfloat162* dst = (__nv_bfloat162*)g_fs_bf;
    dst[2 * i]     = __floats2bfloat162_rn(v0.x, v0.y);
    dst[2 * i + 1] = __floats2bfloat162_rn(v0.z, v0.w);
    dst[2 * i + 2] = __floats2bfloat162_rn(v1.x, v1.y);
    dst[2 * i + 3] = __floats2bfloat162_rn(v1.z, v1.w);
}

// ---------------------------------------------------------------------------
// Helpers
// ---------------------------------------------------------------------------
__device__ __forceinline__ void cp_async16(uint32_t smem_addr, const void* gptr) {
    asm volatile("cp.async.cg.shared.global [%0], [%1], 16;\n"
                 :: "r"(smem_addr), "l"(gptr));
}
__device__ __forceinline__ void cp_commit() { asm volatile("cp.async.commit_group;\n"); }
template <int N> __device__ __forceinline__ void cp_wait() {
    asm volatile("cp.async.wait_group %0;\n" :: "n"(N));
}

__device__ __forceinline__ void mma16816(float* d, const uint32_t* a, uint32_t b0, uint32_t b1) {
    asm volatile(
        "mma.sync.aligned.m16n8k16.row.col.f32.bf16.bf16.f32 "
        "{%0,%1,%2,%3}, {%4,%5,%6,%7}, {%8,%9}, {%0,%1,%2,%3};\n"
        : "+f"(d[0]), "+f"(d[1]), "+f"(d[2]), "+f"(d[3])
        : "r"(a[0]), "r"(a[1]), "r"(a[2]), "r"(a[3]), "r"(b0), "r"(b1));
}

// ---------------------------------------------------------------------------
// Kernel 2: persistent static-range GEMM + segmented min/max.
// 296 CTAs x 256 threads, 2 CTAs/SM. CTA c owns global iters [s, e),
// iter g -> (mtile = g>>8, block j = g&255). One barrier per iter; exp tail
// for iter i-1 runs at top of iter i from parity-buffered sMax/sMin.
// ---------------------------------------------------------------------------
extern __shared__ char smem_raw[];

__global__ __launch_bounds__(256, 2) void k_main(const float* __restrict__ feats) {
    __nv_bfloat16* sA = (__nv_bfloat16*)smem_raw;                  // MTILE x SROW
    __nv_bfloat16* sB = sA + MTILE * SROW;                         // 2 x BLKC x SROW
    float* sMax = (float*)(sB + 2 * BLKC * SROW);                  // [2][128][2]
    float* sMin = sMax + 2 * MTILE * 2;                            // [2][128][2]

    const int tid  = threadIdx.x;
    const int wid  = tid >> 5;
    const int lane = tid & 31;
    const int wm   = wid & 3;       // warp row (0..3)
    const int wn   = wid >> 2;      // warp col (0..1)
    const int g    = lane >> 2;
    const int q    = lane & 3;
    const uint32_t c = blockIdx.x;
    const uint32_t s = range_start(c);
    const uint32_t e = range_start(c + 1);

    auto issueB = [&](int j, int buf) {
        const char* src = (const char*)(g_fs_bf + (size_t)j * BLKC * CDIM);
        __nv_bfloat16* dstb = sB + buf * BLKC * SROW;
        #pragma unroll
        for (int it = 0; it < 8; it++) {
            int idx = tid + it * 256;                // 0..2047
            int r = idx >> 4, ch = idx & 15;
            uint32_t da = (uint32_t)__cvta_generic_to_shared(dstb + r * SROW + ch * 8);
            cp_async16(da, src + (size_t)idx * 16);
        }
        cp_commit();
    };

    auto loadA = [&](int mtile) {
        const int m0 = mtile * MTILE;
        for (int idx = tid; idx < MTILE * CDIM; idx += 256) {
            int r = idx >> 7, cc = idx & 127;
            sA[r * SROW + cc] = __float2bfloat16(feats[(size_t)(m0 + r) * CDIM + cc]);
        }
    };

    uint32_t afr[2][8][4];
    auto loadAfrags = [&]() {
        const int row_off = lane & 15;
        const int col_off = 8 * (lane >> 4);
#pragma unroll
        for (int mi = 0; mi < 2; mi++) {
            const int rm = 32 * wm + 16 * mi + row_off;
#pragma unroll
            for (int ks = 0; ks < 8; ks++) {
                uint32_t addr = (uint32_t)__cvta_generic_to_shared(&sA[rm * SROW + 16 * ks + col_off]);
                asm volatile("ldmatrix.sync.aligned.m8n8.x4.shared.b16 {%0,%1,%2,%3}, [%4];"
                             : "=r"(afr[mi][ks][0]), "=r"(afr[mi][ks][1]),
                               "=r"(afr[mi][ks][2]), "=r"(afr[mi][ks][3])
                             : "r"(addr));
            }
        }
    };

    // Prefetch B for first iter, stage A for first mtile
    issueB(s & 255, s & 1);
    int cur_m = (int)(s >> 8);
    loadA(cur_m);
    __syncthreads();
    loadAfrags();

    // B fragment offsets (bf16 elements): conflict-free (word = 4g+q mod 32)
    uint32_t boff[8];
#pragma unroll
    for (int ni = 0; ni < 8; ni++)
        boff[ni] = (uint32_t)((64 * wn + 8 * ni + g) * SROW + 2 * q);

    float negacc = 0.0f;
    float posval = 0.0f;

    // exp tail for global iter t (mtile == cur_m at call time)
    auto tail = [&](uint32_t t) {
        const int p = (int)(t & 1);
        float mx = fmaxf(sMax[p * 256 + tid * 2], sMax[p * 256 + tid * 2 + 1]);
        float mn = fminf(sMin[p * 256 + tid * 2], sMin[p * 256 + tid * 2 + 1]);
        const int anchor = cur_m * MTILE + tid;
        if ((anchor >> 4) == (int)(t & 255)) posval = expf(mn * INV_TEMP);
        else                                 negacc += expf(mx * INV_TEMP);
    };

    for (uint32_t i = s; i < e; ++i) {
        const int j   = (int)(i & 255);
        const int m   = (int)(i >> 8);
        const int buf = (int)(i & 1);

        cp_wait<0>();
        __syncthreads();             // B(i) visible; all warps done with B(i-1) & sMax(i-1) writes

        if (i + 1 < e) issueB((int)((i + 1) & 255), (int)((i + 1) & 1));

        if (i > s && tid < MTILE) tail(i - 1);

        if (m != cur_m) {
            // flush partials for cur_m (first mtile of this range -> slot t=0)
            if (tid < MTILE) {
                g_flushN[(c * 2 + 0) * MTILE + tid] = negacc;
                g_flushP[(c * 2 + 0) * MTILE + tid] = posval;
                negacc = 0.0f; posval = 0.0f;
            }
            loadA(m);
            __syncthreads();
            loadAfrags();
            cur_m = m;
        }

        const __nv_bfloat16* bbase = sB + buf * BLKC * SROW;

        float vmx[2][2], vmn[2][2];
#pragma unroll
        for (int p = 0; p < 2; p++) {          // two 64-col N passes (reg pressure)
            float acc[2][4][4];
#pragma unroll
            for (int mi = 0; mi < 2; mi++)
#pragma unroll
                for (int n4 = 0; n4 < 4; n4++)
#pragma unroll
                    for (int cc = 0; cc < 4; cc++) acc[mi][n4][cc] = 0.0f;

#pragma unroll
            for (int ks = 0; ks < 8; ks++) {
                const int kc = 16 * ks;
#pragma unroll
                for (int n4 = 0; n4 < 4; n4++) {
                    const __nv_bfloat16* bp = bbase + boff[4 * p + n4];
                    uint32_t b0 = *(const uint32_t*)(bp + kc);
                    uint32_t b1 = *(const uint32_t*)(bp + kc + 8);
                    mma16816(acc[0][n4], afr[0][ks], b0, b1);
                    mma16816(acc[1][n4], afr[1][ks], b0, b1);
                }
            }
#pragma unroll
            for (int mi = 0; mi < 2; mi++) {
#pragma unroll
                for (int h = 0; h < 2; h++) {
                    float mx = -1e30f, mn = 1e30f;
#pragma unroll
                    for (int n4 = 0; n4 < 4; n4++) {
                        float c0 = acc[mi][n4][2 * h];
                        float c1 = acc[mi][n4][2 * h + 1];
                        mx = fmaxf(mx, fmaxf(c0, c1));
                        mn = fminf(mn, fminf(c0, c1));
                    }
                    if (p == 0) { vmx[mi][h] = mx; vmn[mi][h] = mn; }
                    else { vmx[mi][h] = fmaxf(vmx[mi][h], mx); vmn[mi][h] = fminf(vmn[mi][h], mn); }
                }
            }
        }

        // cross-lane (q) reduce + parity-buffered smem partials
#pragma unroll
        for (int mi = 0; mi < 2; mi++) {
#pragma unroll
            for (int h = 0; h < 2; h++) {
                float mx = vmx[mi][h], mn = vmn[mi][h];
                mx = fmaxf(mx, __shfl_xor_sync(0xFFFFFFFFu, mx, 1));
                mx = fmaxf(mx, __shfl_xor_sync(0xFFFFFFFFu, mx, 2));
                mn = fminf(mn, __shfl_xor_sync(0xFFFFFFFFu, mn, 1));
                mn = fminf(mn, __shfl_xor_sync(0xFFFFFFFFu, mn, 2));
                if (q == 0) {
                    int row = 32 * wm + 16 * mi + 8 * h + g;
                    sMax[buf * 256 + row * 2 + wn] = mx;
                    sMin[buf * 256 + row * 2 + wn] = mn;
                }
            }
        }
        // (no second barrier: next iter's sync orders these writes vs. tail reads)
    }

    __syncthreads();
    if (tid < MTILE) {
        tail(e - 1);
        const int t = (cur_m == (int)(s >> 8)) ? 0 : 1;   // final-slot index
        g_flushN[(c * 2 + t) * MTILE + tid] = negacc;
        g_flushP[(c * 2 + t) * MTILE + tid] = posval;
    }
}

// ---------------------------------------------------------------------------
// Kernel 3: gather static flush slots per anchor, loss, deterministic mean
// ---------------------------------------------------------------------------
__global__ void k_final(float* __restrict__ out) {
    __shared__ double red[256];
    const int tid = threadIdx.x;
    double sum = 0.0;
    for (int a = tid; a < BSZ; a += 256) {
        const int m = a >> 7;            // mtile
        const int row = a & 127;
        float neg = 0.0f, pos = 0.0f;
        int c0 = (m * NCTA) / MTILES - 1;
        if (c0 < 0) c0 = 0;
        for (int c = c0; c < NCTA; ++c) {
            uint32_t sc = range_start(c);
            if (sc >= (uint32_t)((m + 1) * PIDS)) break;
            uint32_t ec = range_start(c + 1);
            if (ec <= (uint32_t)(m * PIDS)) continue;
            const int t = ((int)(sc >> 8) == m) ? 0 : 1;
            neg += g_flushN[(c * 2 + t) * MTILE + row];
            pos += g_flushP[(c * 2 + t) * MTILE + row];
        }
        float loss = -logf(pos / (pos + neg + EPSV) + EPSV);
        sum += (double)loss;
    }
    red[tid] = sum;
    __syncthreads();
    for (int o = 128; o > 0; o >>= 1) {
        if (tid < o) red[tid] += red[tid + o];
        __syncthreads();
    }
    if (tid == 0) out[0] = (float)(red[0] / (double)BSZ);
}

// ---------------------------------------------------------------------------
// Launch
// ---------------------------------------------------------------------------
extern "C" void kernel_launch(void* const* d_in, const int* in_sizes, int n_in,
                              void* d_out, int out_size) {
    const float* feats   = (const float*)d_in[0];   // [4096,128] fp32
    const float* feats_s = (const float*)d_in[1];   // [4096,8,128] fp32
    float* out = (float*)d_out;

    // A (34816) + 2xB (69632) + parity min/max (4096) = 108544 B; 2 CTAs/SM
    const int smem_bytes = MTILE * SROW * 2 + 2 * BLKC * SROW * 2 + 2 * MTILE * 2 * 4 * 2;
    cudaFuncSetAttribute(k_main, cudaFuncAttributeMaxDynamicSharedMemorySize, smem_bytes);

    k_convert<<<(NSUP * CDIM / 8) / 256, 256>>>(feats_s);
    k_main<<<NCTA, 256, smem_bytes>>>(feats);
    k_final<<<1, 256>>>(out);
}

// round 12
// speedup vs baseline: 1.2648x; 1.2648x over previous
#include <cuda_runtime.h>
#include <cuda_bf16.h>
#include <cstdint>

// Problem constants
#define BSZ   4096
#define CDIM  128
#define NSUP  32768          // 4096*8 support rows
#define PIDS  256
#define BLKC  128            // support columns per identity block
#define NSPLIT 8
#define BPS   (PIDS/NSPLIT)  // 32 blocks per split
#define MTILE 128
#define MTILES (BSZ/MTILE)   // 32
#define INV_TEMP 20.0f
#define EPSV 1e-6f
#define SROW 136             // smem row stride in bf16 (128+8 pad, conflict-free)

// Scratch (static device globals)
__device__ __nv_bfloat16 g_fs_bf[(size_t)NSUP * CDIM];   // 8 MB (L2-resident)
__device__ float g_negpart[NSPLIT * BSZ];
__device__ float g_pospart[NSPLIT * BSZ];

// ---------------------------------------------------------------------------
// Kernel 1: convert feats_s fp32 -> bf16 (2 float4 per thread)
// ---------------------------------------------------------------------------
__global__ void k_convert(const float* __restrict__ fs) {
    int i = (blockIdx.x * blockDim.x + threadIdx.x) * 2;    // float4 index
    float4 v0 = ((const float4*)fs)[i];
    float4 v1 = ((const float4*)fs)[i + 1];
    __nv_bfloat162* dst = (__nv_bfloat162*)g_fs_bf;
    dst[2 * i]     = __floats2bfloat162_rn(v0.x, v0.y);
    dst[2 * i + 1] = __floats2bfloat162_rn(v0.z, v0.w);
    dst[2 * i + 2] = __floats2bfloat162_rn(v1.x, v1.y);
    dst[2 * i + 3] = __floats2bfloat162_rn(v1.z, v1.w);
}

// ---------------------------------------------------------------------------
// Helpers
// ---------------------------------------------------------------------------
__device__ __forceinline__ void cp_async16(uint32_t smem_addr, const void* gptr) {
    asm volatile("cp.async.cg.shared.global [%0], [%1], 16;\n"
                 :: "r"(smem_addr), "l"(gptr));
}
__device__ __forceinline__ void cp_commit() { asm volatile("cp.async.commit_group;\n"); }
template <int N> __device__ __forceinline__ void cp_wait() {
    asm volatile("cp.async.wait_group %0;\n" :: "n"(N));
}

__device__ __forceinline__ void mma16816(float* d, const uint32_t* a, uint32_t b0, uint32_t b1) {
    asm volatile(
        "mma.sync.aligned.m16n8k16.row.col.f32.bf16.bf16.f32 "
        "{%0,%1,%2,%3}, {%4,%5,%6,%7}, {%8,%9}, {%0,%1,%2,%3};\n"
        : "+f"(d[0]), "+f"(d[1]), "+f"(d[2]), "+f"(d[3])
        : "r"(a[0]), "r"(a[1]), "r"(a[2]), "r"(a[3]), "r"(b0), "r"(b1));
}

// ---------------------------------------------------------------------------
// Kernel 2: fixed-grid tiled bf16 MMA + segmented max (min only on own-iters).
// grid (MTILES, NSPLIT) = 256 CTAs, 256 threads, 2 CTAs/SM.
// One barrier per iter; exp tail for iter jb-1 runs at top of iter jb from
// parity-buffered sMax/sMin.
// ---------------------------------------------------------------------------
extern __shared__ char smem_raw[];

__global__ __launch_bounds__(256, 2) void k_main(const float* __restrict__ feats) {
    __nv_bfloat16* sA = (__nv_bfloat16*)smem_raw;                  // MTILE x SROW
    __nv_bfloat16* sB = sA + MTILE * SROW;                         // 2 x BLKC x SROW
    float* sMax = (float*)(sB + 2 * BLKC * SROW);                  // [2][128][2]
    float* sMin = sMax + 2 * MTILE * 2;                            // [2][128][2]

    const int tid  = threadIdx.x;
    const int wid  = tid >> 5;
    const int lane = tid & 31;
    const int wm   = wid & 3;       // warp row (0..3)
    const int wn   = wid >> 2;      // warp col (0..1)
    const int g    = lane >> 2;
    const int q    = lane & 3;
    const int mtile = blockIdx.x;
    const int m0   = mtile * MTILE;
    const int split = blockIdx.y;
    const int jbase = split * BPS;
    const int own_j0 = mtile * 8;   // this mtile's identities: [own_j0, own_j0+8)

    auto issueB = [&](int j, int buf) {
        const char* src = (const char*)(g_fs_bf + (size_t)j * BLKC * CDIM);
        __nv_bfloat16* dstb = sB + buf * BLKC * SROW;
        #pragma unroll
        for (int it = 0; it < 8; it++) {
            int idx = tid + it * 256;                // 0..2047
            int r = idx >> 4, ch = idx & 15;
            uint32_t da = (uint32_t)__cvta_generic_to_shared(dstb + r * SROW + ch * 8);
            cp_async16(da, src + (size_t)idx * 16);
        }
        cp_commit();
    };
    issueB(jbase, 0);

    // feats tile -> bf16 smem
    for (int idx = tid; idx < MTILE * CDIM; idx += 256) {
        int r = idx >> 7, c = idx & 127;
        sA[r * SROW + c] = __float2bfloat16(feats[(size_t)(m0 + r) * CDIM + c]);
    }
    __syncthreads();

    // Preload A fragments: 32 rows x K=128 per warp (64 regs)
    uint32_t afr[2][8][4];
    {
        const int row_off = lane & 15;
        const int col_off = 8 * (lane >> 4);
#pragma unroll
        for (int mi = 0; mi < 2; mi++) {
            const int rm = 32 * wm + 16 * mi + row_off;
#pragma unroll
            for (int ks = 0; ks < 8; ks++) {
                uint32_t addr = (uint32_t)__cvta_generic_to_shared(&sA[rm * SROW + 16 * ks + col_off]);
                asm volatile("ldmatrix.sync.aligned.m8n8.x4.shared.b16 {%0,%1,%2,%3}, [%4];"
                             : "=r"(afr[mi][ks][0]), "=r"(afr[mi][ks][1]),
                               "=r"(afr[mi][ks][2]), "=r"(afr[mi][ks][3])
                             : "r"(addr));
            }
        }
    }

    // B fragment offsets (bf16 elements): conflict-free (word = 4g+q mod 32)
    uint32_t boff[8];
#pragma unroll
    for (int ni = 0; ni < 8; ni++)
        boff[ni] = (uint32_t)((64 * wn + 8 * ni + g) * SROW + 2 * q);

    float negacc = 0.0f;
    float posval = 0.0f;

    for (int jb = 0; jb < BPS; ++jb) {
        const int j   = jbase + jb;
        const int buf = jb & 1;
        const bool ownIter = (unsigned)(j - own_j0) < 8u;   // uniform

        if (jb + 1 < BPS) { issueB(j + 1, buf ^ 1); cp_wait<1>(); }
        else              { cp_wait<0>(); }
        __syncthreads();      // B(jb) visible; sMax(jb-1) writes ordered before tail reads

        // Deferred exp tail for iter jb-1 (parity pb = (jb-1)&1 = buf^1)
        if (jb > 0 && tid < MTILE) {
            const int pb = buf ^ 1;
            const int pj = j - 1;
            const int anchor = m0 + tid;
            if ((anchor >> 4) == pj) {
                float mn = fminf(sMin[pb * 256 + tid * 2], sMin[pb * 256 + tid * 2 + 1]);
                posval = __expf(mn * INV_TEMP);
            } else {
                float mx = fmaxf(sMax[pb * 256 + tid * 2], sMax[pb * 256 + tid * 2 + 1]);
                negacc += __expf(mx * INV_TEMP);
            }
        }

        const __nv_bfloat16* bbase = sB + buf * BLKC * SROW;

        float vmx[2][2], vmn[2][2];
#pragma unroll
        for (int p = 0; p < 2; p++) {          // two 64-col N passes (reg pressure)
            float acc[2][4][4];
#pragma unroll
            for (int mi = 0; mi < 2; mi++)
#pragma unroll
                for (int n4 = 0; n4 < 4; n4++)
#pragma unroll
                    for (int cc = 0; cc < 4; cc++) acc[mi][n4][cc] = 0.0f;

#pragma unroll
            for (int ks = 0; ks < 8; ks++) {
                const int kc = 16 * ks;
#pragma unroll
                for (int n4 = 0; n4 < 4; n4++) {
                    const __nv_bfloat16* bp = bbase + boff[4 * p + n4];
                    uint32_t b0 = *(const uint32_t*)(bp + kc);
                    uint32_t b1 = *(const uint32_t*)(bp + kc + 8);
                    mma16816(acc[0][n4], afr[0][ks], b0, b1);
                    mma16816(acc[1][n4], afr[1][ks], b0, b1);
                }
            }
            // fold max (always); min only on own-iters (1/128 of all iters)
#pragma unroll
            for (int mi = 0; mi < 2; mi++) {
#pragma unroll
                for (int h = 0; h < 2; h++) {
                    float mx = -1e30f;
#pragma unroll
                    for (int n4 = 0; n4 < 4; n4++)
                        mx = fmaxf(mx, fmaxf(acc[mi][n4][2 * h], acc[mi][n4][2 * h + 1]));
                    if (p == 0) vmx[mi][h] = mx; else vmx[mi][h] = fmaxf(vmx[mi][h], mx);
                }
            }
            if (ownIter) {
#pragma unroll
                for (int mi = 0; mi < 2; mi++) {
#pragma unroll
                    for (int h = 0; h < 2; h++) {
                        float mn = 1e30f;
#pragma unroll
                        for (int n4 = 0; n4 < 4; n4++)
                            mn = fminf(mn, fminf(acc[mi][n4][2 * h], acc[mi][n4][2 * h + 1]));
                        if (p == 0) vmn[mi][h] = mn; else vmn[mi][h] = fminf(vmn[mi][h], mn);
                    }
                }
            }
        }

        // cross-lane (q) reduce + parity-buffered smem partials
#pragma unroll
        for (int mi = 0; mi < 2; mi++) {
#pragma unroll
            for (int h = 0; h < 2; h++) {
                float mx = vmx[mi][h];
                mx = fmaxf(mx, __shfl_xor_sync(0xFFFFFFFFu, mx, 1));
                mx = fmaxf(mx, __shfl_xor_sync(0xFFFFFFFFu, mx, 2));
                if (q == 0) {
                    int row = 32 * wm + 16 * mi + 8 * h + g;
                    sMax[buf * 256 + row * 2 + wn] = mx;
                }
            }
        }
        if (ownIter) {
#pragma unroll
            for (int mi = 0; mi < 2; mi++) {
#pragma unroll
                for (int h = 0; h < 2; h++) {
                    float mn = vmn[mi][h];
                    mn = fminf(mn, __shfl_xor_sync(0xFFFFFFFFu, mn, 1));
                    mn = fminf(mn, __shfl_xor_sync(0xFFFFFFFFu, mn, 2));
                    if (q == 0) {
                        int row = 32 * wm + 16 * mi + 8 * h + g;
                        sMin[buf * 256 + row * 2 + wn] = mn;
                    }
                }
            }
        }
        // (no second barrier: next iter's sync orders these writes vs. tail reads)
    }

    // Drain: tail for last iter (jb = BPS-1, parity (BPS-1)&1)
    __syncthreads();
    if (tid < MTILE) {
        const int pb = (BPS - 1) & 1;
        const int pj = jbase + BPS - 1;
        const int anchor = m0 + tid;
        if ((anchor >> 4) == pj) {
            float mn = fminf(sMin[pb * 256 + tid * 2], sMin[pb * 256 + tid * 2 + 1]);
            posval = __expf(mn * INV_TEMP);
        } else {
            float mx = fmaxf(sMax[pb * 256 + tid * 2], sMax[pb * 256 + tid * 2 + 1]);
            negacc += __expf(mx * INV_TEMP);
        }
        g_negpart[split * BSZ + m0 + tid] = negacc;
        g_pospart[split * BSZ + m0 + tid] = posval;   // 0.0 for non-own splits
    }
}

// ---------------------------------------------------------------------------
// Kernel 3: combine splits, per-anchor loss, deterministic mean
// ---------------------------------------------------------------------------
__global__ void k_final(float* __restrict__ out) {
    __shared__ double red[256];
    int tid = threadIdx.x;
    double s = 0.0;
    for (int a = tid; a < BSZ; a += 256) {
        float neg = 0.0f, pos = 0.0f;
#pragma unroll
        for (int sp = 0; sp < NSPLIT; sp++) {
            neg += g_negpart[sp * BSZ + a];
            pos += g_pospart[sp * BSZ + a];
        }
        float loss = -logf(pos / (pos + neg + EPSV) + EPSV);
        s += (double)loss;
    }
    red[tid] = s;
    __syncthreads();
    for (int o = 128; o > 0; o >>= 1) {
        if (tid < o) red[tid] += red[tid + o];
        __syncthreads();
    }
    if (tid == 0) out[0] = (float)(red[0] / (double)BSZ);
}

// ---------------------------------------------------------------------------
// Launch
// ---------------------------------------------------------------------------
extern "C" void kernel_launch(void* const* d_in, const int* in_sizes, int n_in,
                              void* d_out, int out_size) {
    const float* feats   = (const float*)d_in[0];   // [4096,128] fp32
    const float* feats_s = (const float*)d_in[1];   // [4096,8,128] fp32
    float* out = (float*)d_out;

    // A (34816) + 2xB (69632) + parity min/max (4096) = 108544 B; 2 CTAs/SM
    const int smem_bytes = MTILE * SROW * 2 + 2 * BLKC * SROW * 2 + 2 * MTILE * 2 * 4 * 2;
    cudaFuncSetAttribute(k_main, cudaFuncAttributeMaxDynamicSharedMemorySize, smem_bytes);

    k_convert<<<(NSUP * CDIM / 8) / 256, 256>>>(feats_s);
    dim3 grid(MTILES, NSPLIT);
    k_main<<<grid, 256, smem_bytes>>>(feats);
    k_final<<<1, 256>>>(out);
}